// round 4
// baseline (speedup 1.0000x reference)
#include <cuda_runtime.h>
#include <cstdint>

// out[b,k] = sum_ij in1[b,i]*in2[b,j]*cb[k,ij]
// GEMM via mma.sync.m16n8k8 tf32 (baseline PTX, works for compute_103 target),
// 3xTF32 emulation, runtime 8x8 block-sparsity on cb.
//
// prep: for each of 11x11 (kt=ij-block, nt=kout-block) 8x8 blocks of
//   Bmat[ij][kout] = cb[kout*81+ij], detect nonzero, pack active blocks as
//   per-lane float4 {b0_hi, b1_hi, b0_lo, b1_lo} (b0=B[kt*8+(lane&3)][nt*8+(lane>>2)],
//   b1 = same with +4 on k), slots assigned kt-major/nt-minor; mask[kt] bit nt.
// main: CTA 256 thr, 128 rows. Warp handles 16 rows x all ntiles.
//   A frags computed on the fly from shared in1/in2 (i=(ij*57)>>9, j=ij-9i).
//   Epilogue: D frags -> shared O (reusing B region) -> coalesced STG.128.

#define NKOUT 81
#define NIJ   81
#define NT    11
#define KT    11
#define NBLK  (NT * KT)
#define TPB   256
#define ROWS  128

__device__ float4   g_blk[NBLK * 32];
__device__ unsigned g_mask[KT];
__device__ int      g_nslot;

__device__ __forceinline__ float tf32_rna(float v) {
    unsigned r;
    asm("cvt.rna.tf32.f32 %0, %1;" : "=r"(r) : "f"(v));
    return __uint_as_float(r);
}

__device__ __forceinline__ void mma8(float* d,
                                     unsigned a0, unsigned a1, unsigned a2, unsigned a3,
                                     unsigned b0, unsigned b1) {
    asm volatile(
        "mma.sync.aligned.m16n8k8.row.col.f32.tf32.tf32.f32 "
        "{%0,%1,%2,%3}, {%4,%5,%6,%7}, {%8,%9}, {%0,%1,%2,%3};"
        : "+f"(d[0]), "+f"(d[1]), "+f"(d[2]), "+f"(d[3])
        : "r"(a0), "r"(a1), "r"(a2), "r"(a3), "r"(b0), "r"(b1));
}

__global__ void prep_kernel(const float* __restrict__ cb) {
    __shared__ int      flag[NBLK];
    __shared__ int      slotof[NBLK];
    __shared__ unsigned smask[KT];
    const int tid = threadIdx.x;
    if (tid < KT) smask[tid] = 0;
    __syncthreads();

    const int kt = tid / NT;
    const int nt = tid % NT;
    if (tid < NBLK) {
        int f = 0;
        for (int q = 0; q < 8; q++)
            for (int n = 0; n < 8; n++) {
                int ij = kt * 8 + q, ko = nt * 8 + n;
                float v = (ij < NIJ && ko < NKOUT) ? cb[ko * NIJ + ij] : 0.f;
                if (v != 0.f) f = 1;
            }
        flag[tid] = f;
        if (f) atomicOr(&smask[kt], 1u << nt);
    }
    __syncthreads();
    if (tid == 0) {
        int s = 0;
        for (int b = 0; b < NBLK; b++) { slotof[b] = s; s += flag[b]; }
        g_nslot = s;
    }
    __syncthreads();
    if (tid < KT) g_mask[tid] = smask[tid];
    if (tid < NBLK && flag[tid]) {
        const int slot = slotof[tid];
        for (int L = 0; L < 32; L++) {
            int n = L >> 2, q = L & 3;
            int ko = nt * 8 + n;
            int ij0 = kt * 8 + q, ij1 = ij0 + 4;
            float v0 = (ij0 < NIJ && ko < NKOUT) ? cb[ko * NIJ + ij0] : 0.f;
            float v1 = (ij1 < NIJ && ko < NKOUT) ? cb[ko * NIJ + ij1] : 0.f;
            float h0 = tf32_rna(v0), h1 = tf32_rna(v1);
            g_blk[slot * 32 + L] = make_float4(h0, h1, v0 - h0, v1 - h1);
        }
    }
}

// shared layout (floats): in1s[1160] | in2s[1160] | mask[16 ints] | B blocks
#define IN1_OFF  0
#define IN2_OFF  1160
#define MASK_OFF 2320
#define SB_OFF   2336                     // float4-aligned (2336*4 % 16 == 0)
#define SMEM_FLOATS (SB_OFF + NBLK * 128) // 2336 + 15488 = 17824 -> 71296 B

__global__ void __launch_bounds__(TPB, 3) tp_mma(
    const float* __restrict__ in1,
    const float* __restrict__ in2,
    float* __restrict__ out,
    int B)
{
    extern __shared__ float smem[];
    float*    in1s  = smem + IN1_OFF;
    float*    in2s  = smem + IN2_OFF;
    unsigned* smask = (unsigned*)(smem + MASK_OFF);
    float4*   sB    = (float4*)(smem + SB_OFF);

    const int tid  = threadIdx.x;
    const int base = blockIdx.x * ROWS;

    // stage inputs (zero-pad rows beyond B)
    const int lim = B * 9 - base * 9;
    for (int idx = tid; idx < ROWS * 9; idx += TPB) {
        bool ok = idx < lim;
        in1s[idx] = ok ? in1[base * 9 + idx] : 0.f;
        in2s[idx] = ok ? in2[base * 9 + idx] : 0.f;
    }
    const int nslot = g_nslot;
    for (int idx = tid; idx < nslot * 32; idx += TPB) sB[idx] = g_blk[idx];
    if (tid < KT) smask[tid] = g_mask[tid];
    __syncthreads();

    const int lane = tid & 31;
    const int warp = tid >> 5;
    const int g = lane >> 2;
    const int t = lane & 3;
    const int r0 = warp * 16 + g;   // local row for a0/a2, d0/d1
    const int r1 = r0 + 8;          // local row for a1/a3, d2/d3

    float acc[NT][4];
#pragma unroll
    for (int n = 0; n < NT; n++) {
        acc[n][0] = 0.f; acc[n][1] = 0.f; acc[n][2] = 0.f; acc[n][3] = 0.f;
    }

    const float* a0p = in1s + r0 * 9;
    const float* a1p = in1s + r1 * 9;
    const float* c0p = in2s + r0 * 9;
    const float* c1p = in2s + r1 * 9;

    int slot = 0;
#pragma unroll
    for (int kt = 0; kt < KT; kt++) {
        const int col0 = kt * 8 + t;
        const int col1 = col0 + 4;
        const int i0 = (col0 * 57) >> 9;  const int j0 = col0 - 9 * i0;
        const int i1 = (col1 * 57) >> 9;  const int j1 = col1 - 9 * i1;

        float p0 = a0p[i0] * c0p[j0];     // A(row r0, col0)
        float p1 = a1p[i0] * c1p[j0];     // A(row r1, col0)
        float p2 = a0p[i1] * c0p[j1];     // A(row r0, col1)
        float p3 = a1p[i1] * c1p[j1];     // A(row r1, col1)
        if (col0 >= NIJ) { p0 = 0.f; p1 = 0.f; }
        if (col1 >= NIJ) { p2 = 0.f; p3 = 0.f; }

        const float h0 = tf32_rna(p0), h1 = tf32_rna(p1);
        const float h2 = tf32_rna(p2), h3 = tf32_rna(p3);
        const unsigned ah0 = __float_as_uint(h0), ah1 = __float_as_uint(h1);
        const unsigned ah2 = __float_as_uint(h2), ah3 = __float_as_uint(h3);
        const unsigned al0 = __float_as_uint(p0 - h0), al1 = __float_as_uint(p1 - h1);
        const unsigned al2 = __float_as_uint(p2 - h2), al3 = __float_as_uint(p3 - h3);

        const unsigned m = smask[kt];
#pragma unroll
        for (int nt = 0; nt < NT; nt++) {
            if (m & (1u << nt)) {
                float4 bq = sB[slot * 32 + lane];
                unsigned bh0 = __float_as_uint(bq.x), bh1 = __float_as_uint(bq.y);
                unsigned bl0 = __float_as_uint(bq.z), bl1 = __float_as_uint(bq.w);
                mma8(acc[nt], ah0, ah1, ah2, ah3, bh0, bh1);
                mma8(acc[nt], ah0, ah1, ah2, ah3, bl0, bl1);
                mma8(acc[nt], al0, al1, al2, al3, bh0, bh1);
                slot++;
            }
        }
    }
    __syncthreads();   // all reads of sB done; reuse as O

    float* O = (float*)sB;   // [128][81] packed
    const int ro0 = r0 * NKOUT, ro1 = r1 * NKOUT;
#pragma unroll
    for (int nt = 0; nt < NT; nt++) {
        const int c = nt * 8 + 2 * t;
        if (c < NKOUT)     { O[ro0 + c]     = acc[nt][0]; O[ro1 + c]     = acc[nt][2]; }
        if (c + 1 < NKOUT) { O[ro0 + c + 1] = acc[nt][1]; O[ro1 + c + 1] = acc[nt][3]; }
    }
    __syncthreads();

    const int out_base = base * NKOUT;          // fits in int (85M)
    const int total    = B * NKOUT - out_base;
    if (total >= ROWS * NKOUT) {
        const float4* O4   = (const float4*)O;
        float4*       out4 = (float4*)(out + out_base);   // 128*81*4 B tile: 16B-aligned
        for (int i = tid; i < (ROWS * NKOUT) / 4; i += TPB) out4[i] = O4[i];
    } else {
        for (int i = tid; i < total; i += TPB) out[out_base + i] = O[i];
    }
}

extern "C" void kernel_launch(void* const* d_in, const int* in_sizes, int n_in,
                              void* d_out, int out_size) {
    const float* in1 = (const float*)d_in[0];
    const float* in2 = (const float*)d_in[1];
    const float* cb  = (const float*)d_in[2];
    float* out = (float*)d_out;

    const int B = in_sizes[0] / 9;
    const int grid = (B + ROWS - 1) / ROWS;
    const size_t smem_bytes = SMEM_FLOATS * sizeof(float);   // 71,296 B

    cudaFuncSetAttribute(tp_mma, cudaFuncAttributeMaxDynamicSharedMemorySize,
                         (int)smem_bytes);

    prep_kernel<<<1, 128>>>(cb);
    tp_mma<<<grid, TPB, smem_bytes>>>(in1, in2, out, B);
}

// round 5
// speedup vs baseline: 1.0144x; 1.0144x over previous
#include <cuda_runtime.h>
#include <cuda_fp16.h>
#include <cstdint>

// out[b,k] = sum_ij in1[b,i]*in2[b,j]*cb[k,ij]   (GEMM: out = P @ Bmat)
// mma.sync.m16n8k16 f16 with exact 2-mma product:
//   A_cat = [p_hi (k0..7) | p_lo (k8..15)]  (same 8 ij-cols twice)
//   mma1 B = [b_hi | b_hi], mma2 B = [b_lo | b_lo]
//   sum = (ph+pl)(bh+bl) = exact p*b in fp32 accum.
// Runtime 8x8 block-sparsity on Bmat (11x11 blocks), per-lane packed uint2
// {bh2, bl2}. D fragments stored straight to gmem (t-quad covers full 32B
// sectors -> no shared O staging).

#define NKOUT 81
#define NIJ   81
#define NT    11
#define KT    11
#define NBLK  (NT * KT)
#define TPB   256
#define ROWS  128

__device__ uint2    g_blk[NBLK * 32];
__device__ unsigned g_mask[KT];
__device__ int      g_nslot;

__global__ void prep_kernel(const float* __restrict__ cb) {
    __shared__ int      flag[NBLK];
    __shared__ int      slotof[NBLK];
    __shared__ unsigned smask[KT];
    const int tid = threadIdx.x;
    if (tid < KT) smask[tid] = 0;
    __syncthreads();

    const int kt = tid / NT;
    const int nt = tid % NT;
    if (tid < NBLK) {
        int f = 0;
        for (int q = 0; q < 8; q++)
            for (int n = 0; n < 8; n++) {
                int ij = kt * 8 + q, ko = nt * 8 + n;
                float v = (ij < NIJ && ko < NKOUT) ? cb[ko * NIJ + ij] : 0.f;
                if (v != 0.f) f = 1;
            }
        flag[tid] = f;
        if (f) atomicOr(&smask[kt], 1u << nt);
    }
    __syncthreads();
    if (tid == 0) {
        int s = 0;
        for (int b = 0; b < NBLK; b++) { slotof[b] = s; s += flag[b]; }
        g_nslot = s;
    }
    __syncthreads();
    if (tid < KT) g_mask[tid] = smask[tid];

    if (tid < NBLK && flag[tid]) {
        const int slot = slotof[tid];
        for (int L = 0; L < 32; L++) {
            int g = L >> 2, t = L & 3;         // B frag: b0 = {B[2t][g], B[2t+1][g]}
            int ko  = nt * 8 + g;
            int ij0 = kt * 8 + 2 * t, ij1 = ij0 + 1;
            float v0 = (ij0 < NIJ && ko < NKOUT) ? cb[ko * NIJ + ij0] : 0.f;
            float v1 = (ij1 < NIJ && ko < NKOUT) ? cb[ko * NIJ + ij1] : 0.f;
            __half h0 = __float2half_rn(v0);
            __half h1 = __float2half_rn(v1);
            __half l0 = __float2half_rn(v0 - __half2float(h0));
            __half l1 = __float2half_rn(v1 - __half2float(h1));
            __half2 bh = __halves2half2(h0, h1);
            __half2 bl = __halves2half2(l0, l1);
            uint2 u;
            u.x = *(unsigned*)&bh;
            u.y = *(unsigned*)&bl;
            g_blk[slot * 32 + L] = u;
        }
    }
}

__device__ __forceinline__ void mma16(float* d,
                                      unsigned a0, unsigned a1, unsigned a2, unsigned a3,
                                      unsigned b0, unsigned b1) {
    asm volatile(
        "mma.sync.aligned.m16n8k16.row.col.f32.f16.f16.f32 "
        "{%0,%1,%2,%3}, {%4,%5,%6,%7}, {%8,%9}, {%0,%1,%2,%3};"
        : "+f"(d[0]), "+f"(d[1]), "+f"(d[2]), "+f"(d[3])
        : "r"(a0), "r"(a1), "r"(a2), "r"(a3), "r"(b0), "r"(b1));
}

__device__ __forceinline__ unsigned pack2(float x, float y) {
    __half2 h = __halves2half2(__float2half_rn(x), __float2half_rn(y));
    return *(unsigned*)&h;
}

// shared (floats): in1s[1160] | in2s[1160] | mask[16] | sB blocks (uint2)
#define IN1_OFF  0
#define IN2_OFF  1160
#define MASK_OFF 2320
#define SB_OFF   2336                          // 8B-aligned (2336*4 % 8 == 0)
#define SMEM_FLOATS (SB_OFF + NBLK * 64)       // 2336 + 7744 = 10080 -> 40320 B

__global__ void __launch_bounds__(TPB, 3) tp_mma(
    const float* __restrict__ in1,
    const float* __restrict__ in2,
    float* __restrict__ out,
    int B)
{
    extern __shared__ float smem[];
    float*    in1s  = smem + IN1_OFF;
    float*    in2s  = smem + IN2_OFF;
    unsigned* smask = (unsigned*)(smem + MASK_OFF);
    uint2*    sB    = (uint2*)(smem + SB_OFF);

    const int tid  = threadIdx.x;
    const int base = blockIdx.x * ROWS;

    const int lim = B * 9 - base * 9;
    for (int idx = tid; idx < ROWS * 9; idx += TPB) {
        bool ok = idx < lim;
        in1s[idx] = ok ? in1[base * 9 + idx] : 0.f;
        in2s[idx] = ok ? in2[base * 9 + idx] : 0.f;
    }
    const int nslot = g_nslot;
    for (int idx = tid; idx < nslot * 32; idx += TPB) sB[idx] = g_blk[idx];
    if (tid < KT) smask[tid] = g_mask[tid];
    __syncthreads();

    const int lane = tid & 31;
    const int warp = tid >> 5;
    const int g = lane >> 2;
    const int t = lane & 3;
    const int r0 = warp * 16 + g;
    const int r1 = r0 + 8;

    float acc[NT][4];
#pragma unroll
    for (int n = 0; n < NT; n++) {
        acc[n][0] = 0.f; acc[n][1] = 0.f; acc[n][2] = 0.f; acc[n][3] = 0.f;
    }

    const float* a0p = in1s + r0 * 9;
    const float* a1p = in1s + r1 * 9;
    const float* c0p = in2s + r0 * 9;
    const float* c1p = in2s + r1 * 9;

    int slot = 0;
#pragma unroll
    for (int kt = 0; kt < KT; kt++) {
        const int c0 = kt * 8 + 2 * t;
        const int c1 = c0 + 1;
        const int i0 = (c0 * 57) >> 9;  const int j0 = c0 - 9 * i0;
        const int i1 = (c1 * 57) >> 9;  const int j1 = c1 - 9 * i1;

        float p00 = a0p[i0] * c0p[j0];     // row r0, col c0
        float p10 = a1p[i0] * c1p[j0];     // row r1, col c0
        float p01 = a0p[i1] * c0p[j1];     // row r0, col c1
        float p11 = a1p[i1] * c1p[j1];     // row r1, col c1
        if (c0 >= NIJ) { p00 = 0.f; p10 = 0.f; }
        if (c1 >= NIJ) { p01 = 0.f; p11 = 0.f; }

        // hi parts
        const unsigned ra0 = pack2(p00, p01);
        const unsigned ra1 = pack2(p10, p11);
        // lo residuals (exact split to ~2^-22)
        __half2 h0 = *(__half2*)&ra0;
        __half2 h1 = *(__half2*)&ra1;
        const unsigned ra2 = pack2(p00 - __low2float(h0),  p01 - __high2float(h0));
        const unsigned ra3 = pack2(p10 - __low2float(h1),  p11 - __high2float(h1));

        const unsigned m = smask[kt];
#pragma unroll
        for (int nt = 0; nt < NT; nt++) {
            if (m & (1u << nt)) {
                uint2 bq = sB[slot * 32 + lane];
                mma16(acc[nt], ra0, ra1, ra2, ra3, bq.x, bq.x);  // (ph+pl)*bh
                mma16(acc[nt], ra0, ra1, ra2, ra3, bq.y, bq.y);  // (ph+pl)*bl
                slot++;
            }
        }
    }

    // direct store: t-quad covers one full 32B sector per row per nt
    const int row0 = base + r0;
    const int row1 = base + r1;
    const bool ok0 = row0 < B;
    const bool ok1 = row1 < B;
    float* o0 = out + row0 * NKOUT;
    float* o1 = out + row1 * NKOUT;
#pragma unroll
    for (int nt = 0; nt < NT; nt++) {
        const int c = nt * 8 + 2 * t;
        if (c + 1 < NKOUT) {
            if (ok0) { o0[c] = acc[nt][0]; o0[c + 1] = acc[nt][1]; }
            if (ok1) { o1[c] = acc[nt][2]; o1[c + 1] = acc[nt][3]; }
        } else if (c < NKOUT) {
            if (ok0) o0[c] = acc[nt][0];
            if (ok1) o1[c] = acc[nt][2];
        }
    }
}

extern "C" void kernel_launch(void* const* d_in, const int* in_sizes, int n_in,
                              void* d_out, int out_size) {
    const float* in1 = (const float*)d_in[0];
    const float* in2 = (const float*)d_in[1];
    const float* cb  = (const float*)d_in[2];
    float* out = (float*)d_out;

    const int B = in_sizes[0] / 9;
    const int grid = (B + ROWS - 1) / ROWS;
    const size_t smem_bytes = SMEM_FLOATS * sizeof(float);   // 40,320 B

    cudaFuncSetAttribute(tp_mma, cudaFuncAttributeMaxDynamicSharedMemorySize,
                         (int)smem_bytes);

    prep_kernel<<<1, 128>>>(cb);
    tp_mma<<<grid, TPB, smem_bytes>>>(in1, in2, out, B);
}